// round 5
// baseline (speedup 1.0000x reference)
#include <cuda_runtime.h>
#include <math.h>
#include <stdint.h>

#define BB 16
#define SS 4096
#define HH 768
#define EE 8
#define CHUNKS 32
#define ROWS_PER_BLK 128   // SS/CHUNKS
#define TS 8
#define NTILES 16          // ROWS_PER_BLK/TS
#define TILE_BYTES (TS * HH * 4)   // 24576

// smem layout in floats
#define XS0_OFF  0          // [8][768] = 6144
#define XS1_OFF  6144       // [8][768] = 6144
#define WLO_OFF  12288      // [768][4] = 3072  (e0..e3)
#define WHI_OFF  15360      // [768][4] = 3072  (e4..e7)
#define ASH_OFF  18432      // [8][128] = 1024
#define EXP_OFF  19456      // [4 sp][16] = 64   ([sp][e*2+parity])
#define RED_OFF  19520      // [8 warps][16] = 128
#define BIAS_OFF 19648      // [8]
#define MBAR_OFF 19656      // 2 x u64 = 4 floats (8B aligned: 19656*4=78624)
#define SMEM_FLOATS 19664   // 78656 bytes per CTA -> 2 CTAs/SM

// deterministic cross-block scratch (allocation-free: device globals)
__device__ float g_num[(size_t)BB * CHUNKS * EE * HH];   // 12.6 MB
__device__ float g_den[BB * CHUNKS * EE];
__device__ float g_attn_scratch[(size_t)BB * EE * SS];

typedef unsigned long long u64;

__device__ __forceinline__ u64 pack2(float lo, float hi) {
    u64 r; asm("mov.b64 %0, {%1, %2};" : "=l"(r) : "f"(lo), "f"(hi)); return r;
}
__device__ __forceinline__ void unpack2(u64 v, float& lo, float& hi) {
    asm("mov.b64 {%0, %1}, %2;" : "=f"(lo), "=f"(hi) : "l"(v));
}
__device__ __forceinline__ void ffma2(u64& d, u64 a, u64 b) {
    asm("fma.rn.f32x2 %0, %1, %2, %3;" : "=l"(d) : "l"(a), "l"(b), "l"(d));
}

__device__ __forceinline__ void mbar_init(uint32_t mbar, uint32_t cnt) {
    asm volatile("mbarrier.init.shared.b64 [%0], %1;" :: "r"(mbar), "r"(cnt) : "memory");
}
__device__ __forceinline__ void mbar_expect_tx(uint32_t mbar, uint32_t bytes) {
    asm volatile("mbarrier.arrive.expect_tx.shared.b64 _, [%0], %1;"
                 :: "r"(mbar), "r"(bytes) : "memory");
}
__device__ __forceinline__ void mbar_wait(uint32_t mbar, uint32_t parity) {
    asm volatile(
        "{\n\t.reg .pred P1;\n\t"
        "WAIT_%=:\n\t"
        "mbarrier.try_wait.parity.acquire.cta.shared::cta.b64 P1, [%0], %1, 0x989680;\n\t"
        "@P1 bra.uni DONE_%=;\n\t"
        "bra.uni WAIT_%=;\n\t"
        "DONE_%=:\n\t}"
        :: "r"(mbar), "r"(parity) : "memory");
}
__device__ __forceinline__ void bulk_g2s(uint32_t dst, const void* src,
                                         uint32_t bytes, uint32_t mbar) {
    asm volatile(
        "cp.async.bulk.shared::cluster.global.mbarrier::complete_tx::bytes "
        "[%0], [%1], %2, [%3];"
        :: "r"(dst), "l"(src), "r"(bytes), "r"(mbar) : "memory");
}
__device__ __forceinline__ uint32_t smem_u32(const void* p) {
    uint32_t a;
    asm("{ .reg .u64 t; cvta.to.shared.u64 t, %1; cvt.u32.u64 %0, t; }" : "=r"(a) : "l"(p));
    return a;
}

template <int HALF>
__device__ __forceinline__ void red_round(float* v, int lane) {
    bool hi = (lane & HALF) != 0;
#pragma unroll
    for (int m = 0; m < HALF; m++) {
        float mine  = hi ? v[m + HALF] : v[m];
        float yours = hi ? v[m]        : v[m + HALF];
        v[m] = mine + __shfl_xor_sync(0xffffffffu, yours, HALF);
    }
}

__global__ __launch_bounds__(256, 2)
void fused_attn_pass1(const float* __restrict__ x,
                      const float* __restrict__ W,
                      const float* __restrict__ bias,
                      float* __restrict__ attn_out)
{
    extern __shared__ float sm[];
    float* wlo     = sm + WLO_OFF;
    float* whi     = sm + WHI_OFF;
    float* a_sh    = sm + ASH_OFF;
    float* exp_sh  = sm + EXP_OFF;
    float* red_sh  = sm + RED_OFF;
    float* bias_sh = sm + BIAS_OFF;

    const int t     = threadIdx.x;
    const int chunk = blockIdx.x;   // 0..31
    const int b     = blockIdx.y;   // 0..15
    const int lane  = t & 31;
    const int warp  = t >> 5;

    const uint32_t smem_base = smem_u32(sm);
    const uint32_t xs_addr[2] = { smem_base + XS0_OFF * 4u, smem_base + XS1_OFF * 4u };
    const uint32_t mb_addr[2] = { smem_base + MBAR_OFF * 4u, smem_base + MBAR_OFF * 4u + 8u };

    // ---- init mbarriers, stage W (transposed [h][e]) and bias ----
    if (t == 0) { mbar_init(mb_addr[0], 1); mbar_init(mb_addr[1], 1); }
    for (int i = t; i < EE * HH; i += 256) {
        int e = i / HH, h = i % HH;
        float v = W[i];
        if (e < 4) wlo[h * 4 + e]       = v;
        else       whi[h * 4 + (e - 4)] = v;
    }
    if (t < EE) bias_sh[t] = bias[t];

    const int hg = t & 63;   // h-split group (64 wide, 2 warps)
    const int sg = t >> 6;   // s-group: 2 rows each (TS=8)

    u64 accp[EE][3];
#pragma unroll
    for (int e = 0; e < EE; e++) { accp[e][0] = 0ull; accp[e][1] = 0ull; accp[e][2] = 0ull; }
    float den_reg = 0.f;

    const float* xbase = x + ((size_t)b * SS + (size_t)chunk * ROWS_PER_BLK) * HH;

    __syncthreads();

    // prefetch tile 0
    if (t == 0) {
        mbar_expect_tx(mb_addr[0], TILE_BYTES);
        bulk_g2s(xs_addr[0], xbase, TILE_BYTES, mb_addr[0]);
    }

    for (int tile = 0; tile < NTILES; tile++) {
        const int bi = tile & 1;
        // prefetch next tile into the other buffer (its previous consumers
        // finished at the end-of-tile __syncthreads of iteration tile-1)
        if (t == 0 && tile + 1 < NTILES) {
            int nb = (tile + 1) & 1;
            mbar_expect_tx(mb_addr[nb], TILE_BYTES);
            bulk_g2s(xs_addr[nb], xbase + (size_t)(tile + 1) * TS * HH,
                     TILE_BYTES, mb_addr[nb]);
        }
        mbar_wait(mb_addr[bi], (tile >> 1) & 1);
        const float* xs = sm + (bi ? XS1_OFF : XS0_OFF);

        // ---- phase A: packed logits, acc2[epair][sl] (f32x2 over e-pairs) ----
        u64 acc2[4][2];
#pragma unroll
        for (int p = 0; p < 4; p++) { acc2[p][0] = 0ull; acc2[p][1] = 0ull; }

#pragma unroll
        for (int j = 0; j < 12; j++) {
            int h = hg + 64 * j;
            ulonglong2 wl = *(const ulonglong2*)&wlo[h << 2];  // (e0,e1),(e2,e3)
            ulonglong2 wh = *(const ulonglong2*)&whi[h << 2];  // (e4,e5),(e6,e7)
            float xv0 = xs[(2 * sg + 0) * HH + h];
            float xv1 = xs[(2 * sg + 1) * HH + h];
            u64 xp0 = pack2(xv0, xv0);
            u64 xp1 = pack2(xv1, xv1);
            ffma2(acc2[0][0], wl.x, xp0); ffma2(acc2[0][1], wl.x, xp1);
            ffma2(acc2[1][0], wl.y, xp0); ffma2(acc2[1][1], wl.y, xp1);
            ffma2(acc2[2][0], wh.x, xp0); ffma2(acc2[2][1], wh.x, xp1);
            ffma2(acc2[3][0], wh.y, xp0); ffma2(acc2[3][1], wh.y, xp1);
        }

        // unpack to acc[16], index m = e*2 + sl
        float acc[16];
#pragma unroll
        for (int p = 0; p < 4; p++) {
            float e0, e1, f0, f1;
            unpack2(acc2[p][0], e0, e1);   // (e=2p, sl=0), (e=2p+1, sl=0)
            unpack2(acc2[p][1], f0, f1);   // (e=2p, sl=1), (e=2p+1, sl=1)
            acc[(2 * p) * 2 + 0]     = e0;
            acc[(2 * p + 1) * 2 + 0] = e1;
            acc[(2 * p) * 2 + 1]     = f0;
            acc[(2 * p + 1) * 2 + 1] = f1;
        }

        // butterfly: rounds 8/4/2/1 then cross-half add -> lane holds acc[lane&15]
        red_round<8>(acc, lane);
        red_round<4>(acc, lane);
        red_round<2>(acc, lane);
        red_round<1>(acc, lane);
        acc[0] += __shfl_xor_sync(0xffffffffu, acc[0], 16);
        if (lane < 16) red_sh[warp * 16 + lane] = acc[0];
        __syncthreads();

        // ---- assemble: combine warp pairs, add bias, exp ----
        if (t < 64) {
            int sgf = t >> 4;          // s-group
            int m   = t & 15;          // e*2 + sl
            int e   = m >> 1;
            int sl  = m & 1;
            float a = red_sh[(2 * sgf) * 16 + m] + red_sh[(2 * sgf + 1) * 16 + m] + bias_sh[e];
            int st = 2 * sgf + sl;     // row within tile
            a_sh[e * 128 + tile * TS + st] = a;
            exp_sh[(st >> 1) * 16 + e * 2 + (st & 1)] = __expf(a);
        }
        __syncthreads();

        // ---- phase B: packed rank-1 accumulate over s-pairs ----
        if (t < 8) {
            float d = 0.f;
#pragma unroll
            for (int s = 0; s < TS; s++)
                d += exp_sh[(s >> 1) * 16 + t * 2 + (s & 1)];
            den_reg += d;
        }
#pragma unroll
        for (int sp = 0; sp < 4; sp++) {
            const ulonglong2* eq = (const ulonglong2*)&exp_sh[sp * 16];
            ulonglong2 q0 = eq[0];  // e0 (s,s+1), e1
            ulonglong2 q1 = eq[1];  // e2, e3
            ulonglong2 q2 = eq[2];  // e4, e5
            ulonglong2 q3 = eq[3];  // e6, e7
            u64 xa = pack2(xs[(2 * sp) * HH + t],       xs[(2 * sp + 1) * HH + t]);
            u64 xb = pack2(xs[(2 * sp) * HH + t + 256], xs[(2 * sp + 1) * HH + t + 256]);
            u64 xc = pack2(xs[(2 * sp) * HH + t + 512], xs[(2 * sp + 1) * HH + t + 512]);
            ffma2(accp[0][0], q0.x, xa); ffma2(accp[0][1], q0.x, xb); ffma2(accp[0][2], q0.x, xc);
            ffma2(accp[1][0], q0.y, xa); ffma2(accp[1][1], q0.y, xb); ffma2(accp[1][2], q0.y, xc);
            ffma2(accp[2][0], q1.x, xa); ffma2(accp[2][1], q1.x, xb); ffma2(accp[2][2], q1.x, xc);
            ffma2(accp[3][0], q1.y, xa); ffma2(accp[3][1], q1.y, xb); ffma2(accp[3][2], q1.y, xc);
            ffma2(accp[4][0], q2.x, xa); ffma2(accp[4][1], q2.x, xb); ffma2(accp[4][2], q2.x, xc);
            ffma2(accp[5][0], q2.y, xa); ffma2(accp[5][1], q2.y, xb); ffma2(accp[5][2], q2.y, xc);
            ffma2(accp[6][0], q3.x, xa); ffma2(accp[6][1], q3.x, xb); ffma2(accp[6][2], q3.x, xc);
            ffma2(accp[7][0], q3.y, xa); ffma2(accp[7][1], q3.y, xb); ffma2(accp[7][2], q3.y, xc);
        }
        __syncthreads();   // buffer consumable again + exp/red reuse
    }

    // ---- epilogue: coalesced atten write + per-block partials ----
    for (int f = t; f < EE * ROWS_PER_BLK; f += 256) {
        int e = f >> 7, i = f & 127;
        attn_out[((size_t)b * EE + e) * SS + chunk * ROWS_PER_BLK + i] = a_sh[f];
    }
    int blk = b * CHUNKS + chunk;
#pragma unroll
    for (int e = 0; e < EE; e++)
#pragma unroll
        for (int k = 0; k < 3; k++) {
            float lo, hi;
            unpack2(accp[e][k], lo, hi);
            g_num[((size_t)blk * EE + e) * HH + t + 256 * k] = lo + hi;
        }
    if (t < EE) g_den[blk * EE + t] = den_reg;
}

__global__ __launch_bounds__(256)
void fused_attn_pass2(float* __restrict__ out)
{
    int e = blockIdx.y, b = blockIdx.z;
    int h = blockIdx.x * 256 + threadIdx.x;   // 0..767

    float den = 0.f;
#pragma unroll
    for (int c = 0; c < CHUNKS; c++) den += g_den[(b * CHUNKS + c) * EE + e];
    float inv = 1.0f / den;

    const float* base = g_num + ((size_t)(b * CHUNKS) * EE + e) * HH + h;
    float s = 0.f;
#pragma unroll
    for (int c = 0; c < CHUNKS; c++)
        s += base[(size_t)c * EE * HH];
    out[((size_t)b * EE + e) * HH + h] = s * inv;
}

extern "C" void kernel_launch(void* const* d_in, const int* in_sizes, int n_in,
                              void* d_out, int out_size)
{
    const float* x    = (const float*)d_in[0];
    const float* W    = (const float*)d_in[1];
    const float* bias = (const float*)d_in[2];

    float* out_f = (float*)d_out;
    float* out_ptr;
    float* attn_ptr;

    const int OUT_N  = BB * EE * HH;          // 98304
    const int ATTN_N = BB * EE * SS;          // 524288

    if (out_size >= OUT_N + ATTN_N) {
        out_ptr  = out_f;
        attn_ptr = out_f + OUT_N;
    } else if (out_size == ATTN_N) {
        out_ptr  = nullptr;
        attn_ptr = out_f;
    } else {
        out_ptr  = out_f;
        float* dev_scratch;
        cudaGetSymbolAddress((void**)&dev_scratch, g_attn_scratch);
        attn_ptr = dev_scratch;
    }
    if (!out_ptr) {
        float* dev_scratch;
        cudaGetSymbolAddress((void**)&dev_scratch, g_attn_scratch);
        out_ptr = dev_scratch;
    }

    size_t smem_bytes = (size_t)SMEM_FLOATS * sizeof(float);
    cudaFuncSetAttribute(fused_attn_pass1,
                         cudaFuncAttributeMaxDynamicSharedMemorySize, (int)smem_bytes);

    fused_attn_pass1<<<dim3(CHUNKS, BB), 256, smem_bytes>>>(x, W, bias, attn_ptr);
    fused_attn_pass2<<<dim3(3, EE, BB), 256>>>(out_ptr);
}

// round 6
// speedup vs baseline: 1.2440x; 1.2440x over previous
#include <cuda_runtime.h>
#include <math.h>
#include <stdint.h>

#define BB 16
#define SS 4096
#define HH 768
#define EE 8
#define CHUNKS 32
#define ROWS_PER_BLK 128
#define TS 8
#define NTILES 16
#define NBUF 3
#define NEB 4
#define TILE_BYTES (TS * HH * 4)   // 24576
#define XS_STRIDE 6144             // floats per x buffer

// smem layout in floats
#define XS_OFF    0                // 3 x 6144 = 18432
#define WLO_OFF   18432            // [768][4] = 3072
#define WHI_OFF   21504            // [768][4] = 3072
#define ASH_OFF   24576            // [8][128] = 1024
#define EXPPK_OFF 25600            // NEB x 64 u64 = 512 floats (8B aligned)
#define RED_OFF   26112            // [4 warps][32] = 128
#define BIAS_OFF  26240            // [8]
#define DENP_OFF  26248            // [64]
#define MBAR_OFF  26312            // 14 barriers x 8B = 28 floats (8B aligned)
#define SMEM_FLOATS 26344          // 105376 bytes -> 2 CTAs/SM

__device__ float g_num[(size_t)BB * CHUNKS * EE * HH];
__device__ float g_den[BB * CHUNKS * EE];
__device__ float g_attn_scratch[(size_t)BB * EE * SS];

typedef unsigned long long u64;

__device__ __forceinline__ u64 pack2(float lo, float hi) {
    u64 r; asm("mov.b64 %0, {%1, %2};" : "=l"(r) : "f"(lo), "f"(hi)); return r;
}
__device__ __forceinline__ void unpack2(u64 v, float& lo, float& hi) {
    asm("mov.b64 {%0, %1}, %2;" : "=f"(lo), "=f"(hi) : "l"(v));
}
__device__ __forceinline__ void ffma2(u64& d, u64 a, u64 b) {
    asm("fma.rn.f32x2 %0, %1, %2, %3;" : "=l"(d) : "l"(a), "l"(b), "l"(d));
}
__device__ __forceinline__ void mbar_init(uint32_t mbar, uint32_t cnt) {
    asm volatile("mbarrier.init.shared.b64 [%0], %1;" :: "r"(mbar), "r"(cnt) : "memory");
}
__device__ __forceinline__ void mbar_expect_tx(uint32_t mbar, uint32_t bytes) {
    asm volatile("mbarrier.arrive.expect_tx.shared.b64 _, [%0], %1;"
                 :: "r"(mbar), "r"(bytes) : "memory");
}
__device__ __forceinline__ void mbar_arrive(uint32_t mbar) {
    asm volatile("mbarrier.arrive.shared.b64 _, [%0];" :: "r"(mbar) : "memory");
}
__device__ __forceinline__ void mbar_wait(uint32_t mbar, uint32_t parity) {
    asm volatile(
        "{\n\t.reg .pred P1;\n\t"
        "WAIT_%=:\n\t"
        "mbarrier.try_wait.parity.acquire.cta.shared::cta.b64 P1, [%0], %1, 0x989680;\n\t"
        "@P1 bra.uni DONE_%=;\n\t"
        "bra.uni WAIT_%=;\n\t"
        "DONE_%=:\n\t}"
        :: "r"(mbar), "r"(parity) : "memory");
}
__device__ __forceinline__ void bulk_g2s(uint32_t dst, const void* src,
                                         uint32_t bytes, uint32_t mbar) {
    asm volatile(
        "cp.async.bulk.shared::cluster.global.mbarrier::complete_tx::bytes "
        "[%0], [%1], %2, [%3];"
        :: "r"(dst), "l"(src), "r"(bytes), "r"(mbar) : "memory");
}
__device__ __forceinline__ uint32_t smem_u32(const void* p) {
    uint32_t a;
    asm("{ .reg .u64 t; cvta.to.shared.u64 t, %1; cvt.u32.u64 %0, t; }" : "=r"(a) : "l"(p));
    return a;
}

template <int HALF>
__device__ __forceinline__ void red_round(float* v, int lane) {
    bool hi = (lane & HALF) != 0;
#pragma unroll
    for (int m = 0; m < HALF; m++) {
        float mine  = hi ? v[m + HALF] : v[m];
        float yours = hi ? v[m]        : v[m + HALF];
        v[m] = mine + __shfl_xor_sync(0xffffffffu, yours, HALF);
    }
}

__global__ __launch_bounds__(256, 2)
void fused_attn_pass1(const float* __restrict__ x,
                      const float* __restrict__ W,
                      const float* __restrict__ bias,
                      float* __restrict__ attn_out)
{
    extern __shared__ float sm[];
    float* wlo     = sm + WLO_OFF;
    float* whi     = sm + WHI_OFF;
    float* a_sh    = sm + ASH_OFF;
    u64*   exp_pk  = (u64*)(sm + EXPPK_OFF);
    float* red_sh  = sm + RED_OFF;
    float* bias_sh = sm + BIAS_OFF;
    float* den_sh  = sm + DENP_OFF;

    const int t     = threadIdx.x;
    const int chunk = blockIdx.x;
    const int b     = blockIdx.y;
    const int lane  = t & 31;
    const int warp  = t >> 5;

    const uint32_t smem_base = smem_u32(sm);
    const uint32_t MB = smem_base + MBAR_OFF * 4u;
    // full[0..2]=MB+0,8,16  empty[0..2]=MB+24..  expfull[0..3]=MB+48..  expempty[0..3]=MB+80..
#define FULL_MB(i)     (MB + (i) * 8u)
#define EMPTY_MB(i)    (MB + 24u + (i) * 8u)
#define EXPFULL_MB(i)  (MB + 48u + (i) * 8u)
#define EXPEMPTY_MB(i) (MB + 80u + (i) * 8u)

    if (t == 0) {
#pragma unroll
        for (int i = 0; i < NBUF; i++) { mbar_init(FULL_MB(i), 1); mbar_init(EMPTY_MB(i), 256); }
#pragma unroll
        for (int i = 0; i < NEB; i++)  { mbar_init(EXPFULL_MB(i), 64); mbar_init(EXPEMPTY_MB(i), 128); }
    }
    // stage W transposed [h][e] split in two 4-wide halves, + bias
    for (int i = t; i < EE * HH; i += 256) {
        int e = i / HH, h = i % HH;
        float v = W[i];
        if (e < 4) wlo[h * 4 + e]       = v;
        else       whi[h * 4 + (e - 4)] = v;
    }
    if (t < EE) bias_sh[t] = bias[t];

    const float* xbase = x + ((size_t)b * SS + (size_t)chunk * ROWS_PER_BLK) * HH;
    __syncthreads();

    if (t == 128) {   // producer prologue: fill the 3-deep ring
#pragma unroll
        for (int k = 0; k < NBUF; k++) {
            mbar_expect_tx(FULL_MB(k), TILE_BYTES);
            bulk_g2s(smem_base + (XS_OFF + k * XS_STRIDE) * 4u,
                     xbase + (size_t)k * TS * HH, TILE_BYTES, FULL_MB(k));
        }
    }

    if (t < 128) {
        // ================= A-group: logits + softmax weights =================
        const int hg = t & 63;         // h-slice (64 wide, warp pair)
        const int sg = t >> 6;         // s-group: 4 rows each
        float den_part = 0.f;

        for (int tile = 0; tile < NTILES; tile++) {
            const int buf   = tile % NBUF;
            const int stage = tile & (NEB - 1);
            mbar_wait(FULL_MB(buf), (tile / NBUF) & 1);
            const float* xs = sm + XS_OFF + buf * XS_STRIDE;

            u64 acc2[4][4];
#pragma unroll
            for (int p = 0; p < 4; p++)
#pragma unroll
                for (int sl = 0; sl < 4; sl++) acc2[p][sl] = 0ull;

#pragma unroll
            for (int j = 0; j < 12; j++) {
                int h = hg + 64 * j;
                ulonglong2 wl = *(const ulonglong2*)&wlo[h << 2];
                ulonglong2 wh = *(const ulonglong2*)&whi[h << 2];
                u64 xp[4];
#pragma unroll
                for (int sl = 0; sl < 4; sl++) {
                    float xv = xs[(4 * sg + sl) * HH + h];
                    xp[sl] = pack2(xv, xv);
                }
#pragma unroll
                for (int sl = 0; sl < 4; sl++) {
                    ffma2(acc2[0][sl], wl.x, xp[sl]);
                    ffma2(acc2[1][sl], wl.y, xp[sl]);
                    ffma2(acc2[2][sl], wh.x, xp[sl]);
                    ffma2(acc2[3][sl], wh.y, xp[sl]);
                }
            }
            mbar_arrive(EMPTY_MB(buf));    // done reading xs

            float acc[32];
#pragma unroll
            for (int p = 0; p < 4; p++)
#pragma unroll
                for (int sl = 0; sl < 4; sl++)
                    unpack2(acc2[p][sl], acc[(2 * p) * 4 + sl], acc[(2 * p + 1) * 4 + sl]);

            red_round<16>(acc, lane);
            red_round<8>(acc, lane);
            red_round<4>(acc, lane);
            red_round<2>(acc, lane);
            red_round<1>(acc, lane);
            red_sh[warp * 32 + lane] = acc[0];   // warp-partial for m=lane
            asm volatile("bar.sync 1, 128;" ::: "memory");

            if (t < 64) {
                mbar_wait(EXPEMPTY_MB(stage), ((tile / NEB) ^ 1) & 1);
                int sgf = t >> 5;
                int m   = t & 31;
                int e   = m >> 2;
                int sl  = m & 3;
                float a = red_sh[(2 * sgf) * 32 + m] + red_sh[(2 * sgf + 1) * 32 + m]
                          + bias_sh[e];
                int s_local = 4 * sgf + sl;
                a_sh[e * 128 + tile * TS + s_local] = a;
                float ev = __expf(a);
                den_part += ev;
                exp_pk[stage * 64 + s_local * 8 + e] = pack2(ev, ev);
                mbar_arrive(EXPFULL_MB(stage));
            }
            asm volatile("bar.sync 1, 128;" ::: "memory");   // red_sh reuse next tile
        }
        if (t < 64) den_sh[t] = den_part;
    } else {
        // ================= B-group: weighted accumulation =================
        const int tb = t - 128;        // 0..127, owns h = 2*tb + 256k (+1)
        u64 accp[EE][3];
#pragma unroll
        for (int e = 0; e < EE; e++) { accp[e][0] = 0ull; accp[e][1] = 0ull; accp[e][2] = 0ull; }

        for (int tile = 0; tile < NTILES; tile++) {
            const int buf   = tile % NBUF;
            const int stage = tile & (NEB - 1);
            mbar_wait(EXPFULL_MB(stage), (tile / NEB) & 1);
            mbar_wait(FULL_MB(buf), (tile / NBUF) & 1);     // usually already passed
            const float* xs = sm + XS_OFF + buf * XS_STRIDE;
            const ulonglong2* eb = (const ulonglong2*)(exp_pk + stage * 64);

#pragma unroll
            for (int s = 0; s < TS; s++) {
                ulonglong2 q0 = eb[s * 4 + 0];   // (e0,e0),(e1,e1)
                ulonglong2 q1 = eb[s * 4 + 1];
                ulonglong2 q2 = eb[s * 4 + 2];
                ulonglong2 q3 = eb[s * 4 + 3];
                u64 x0 = *(const u64*)&xs[s * HH + 2 * tb];
                u64 x1 = *(const u64*)&xs[s * HH + 2 * tb + 256];
                u64 x2 = *(const u64*)&xs[s * HH + 2 * tb + 512];
                ffma2(accp[0][0], q0.x, x0); ffma2(accp[0][1], q0.x, x1); ffma2(accp[0][2], q0.x, x2);
                ffma2(accp[1][0], q0.y, x0); ffma2(accp[1][1], q0.y, x1); ffma2(accp[1][2], q0.y, x2);
                ffma2(accp[2][0], q1.x, x0); ffma2(accp[2][1], q1.x, x1); ffma2(accp[2][2], q1.x, x2);
                ffma2(accp[3][0], q1.y, x0); ffma2(accp[3][1], q1.y, x1); ffma2(accp[3][2], q1.y, x2);
                ffma2(accp[4][0], q2.x, x0); ffma2(accp[4][1], q2.x, x1); ffma2(accp[4][2], q2.x, x2);
                ffma2(accp[5][0], q2.y, x0); ffma2(accp[5][1], q2.y, x1); ffma2(accp[5][2], q2.y, x2);
                ffma2(accp[6][0], q3.x, x0); ffma2(accp[6][1], q3.x, x1); ffma2(accp[6][2], q3.x, x2);
                ffma2(accp[7][0], q3.y, x0); ffma2(accp[7][1], q3.y, x1); ffma2(accp[7][2], q3.y, x2);
            }
            mbar_arrive(EMPTY_MB(buf));
            mbar_arrive(EXPEMPTY_MB(stage));

            // producer: refill this buffer with tile+NBUF once fully released
            if (t == 128 && tile + NBUF < NTILES) {
                mbar_wait(EMPTY_MB(buf), (tile / NBUF) & 1);
                mbar_expect_tx(FULL_MB(buf), TILE_BYTES);
                bulk_g2s(smem_base + (XS_OFF + buf * XS_STRIDE) * 4u,
                         xbase + (size_t)(tile + NBUF) * TS * HH, TILE_BYTES, FULL_MB(buf));
            }
        }

        // write per-block numerator partials: h = 2*tb + 256k
        int blk = b * CHUNKS + chunk;
#pragma unroll
        for (int e = 0; e < EE; e++)
#pragma unroll
            for (int k = 0; k < 3; k++) {
                float lo, hi;
                unpack2(accp[e][k], lo, hi);
                float2 v = make_float2(lo, hi);
                *(float2*)&g_num[((size_t)blk * EE + e) * HH + 2 * tb + 256 * k] = v;
            }
    }

    __syncthreads();

    // atten logits: coalesced write from a_sh
    for (int f = t; f < EE * ROWS_PER_BLK; f += 256) {
        int e = f >> 7, i = f & 127;
        attn_out[((size_t)b * EE + e) * SS + chunk * ROWS_PER_BLK + i] = a_sh[f];
    }
    // denominator: 8 partials per e in den_sh
    if (t < EE) {
        float d = 0.f;
#pragma unroll
        for (int sgf = 0; sgf < 2; sgf++)
#pragma unroll
            for (int sl = 0; sl < 4; sl++)
                d += den_sh[sgf * 32 + t * 4 + sl];
        g_den[(b * CHUNKS + chunk) * EE + t] = d;
    }
}

__global__ __launch_bounds__(512)
void fused_attn_pass2(float* __restrict__ out)
{
    __shared__ float ps[4][HH];
    __shared__ float inv_sh;

    const int be = blockIdx.x;     // b*8 + e
    const int b = be >> 3, e = be & 7;
    const int t = threadIdx.x;
    const int cg = t >> 7;         // 0..3: chunk group of 8
    const int hl = t & 127;

    if (t == 0) {
        float den = 0.f;
#pragma unroll
        for (int c = 0; c < CHUNKS; c++) den += g_den[(b * CHUNKS + c) * EE + e];
        inv_sh = 1.0f / den;
    }

#pragma unroll
    for (int hb = 0; hb < 6; hb++) {
        int h = hb * 128 + hl;
        const float* base = g_num + ((size_t)(b * CHUNKS + cg * 8) * EE + e) * HH + h;
        float s = 0.f;
#pragma unroll
        for (int c = 0; c < 8; c++)
            s += base[(size_t)c * EE * HH];
        ps[cg][h] = s;
    }
    __syncthreads();

    float inv = inv_sh;
    for (int idx = t; idx < HH; idx += 512)
        out[((size_t)b * EE + e) * HH + idx] =
            (ps[0][idx] + ps[1][idx] + ps[2][idx] + ps[3][idx]) * inv;
}

extern "C" void kernel_launch(void* const* d_in, const int* in_sizes, int n_in,
                              void* d_out, int out_size)
{
    const float* x    = (const float*)d_in[0];
    const float* W    = (const float*)d_in[1];
    const float* bias = (const float*)d_in[2];

    float* out_f = (float*)d_out;
    float* out_ptr;
    float* attn_ptr;

    const int OUT_N  = BB * EE * HH;          // 98304
    const int ATTN_N = BB * EE * SS;          // 524288

    if (out_size >= OUT_N + ATTN_N) {
        out_ptr  = out_f;
        attn_ptr = out_f + OUT_N;
    } else if (out_size == ATTN_N) {
        out_ptr  = nullptr;
        attn_ptr = out_f;
    } else {
        out_ptr  = out_f;
        float* dev_scratch;
        cudaGetSymbolAddress((void**)&dev_scratch, g_attn_scratch);
        attn_ptr = dev_scratch;
    }
    if (!out_ptr) {
        float* dev_scratch;
        cudaGetSymbolAddress((void**)&dev_scratch, g_attn_scratch);
        out_ptr = dev_scratch;
    }

    size_t smem_bytes = (size_t)SMEM_FLOATS * sizeof(float);
    cudaFuncSetAttribute(fused_attn_pass1,
                         cudaFuncAttributeMaxDynamicSharedMemorySize, (int)smem_bytes);

    fused_attn_pass1<<<dim3(CHUNKS, BB), 256, smem_bytes>>>(x, W, bias, attn_ptr);
    fused_attn_pass2<<<BB * EE, 512>>>(out_ptr);
}